// round 13
// baseline (speedup 1.0000x reference)
#include <cuda_runtime.h>
#include <cuda_fp16.h>
#include <math.h>

// Problem constants
#define NN 50000
#define EE 800000
#define FF 2
#define DD 2
#define HH 64
#define TT 12
#define HZ 12

// ---------------- scratch (static device globals; no allocation) ----------------
__device__ __align__(256) int    g_deg[NN];        // zeroed at end of each launch
__device__ __align__(256) int    g_rowptr[NN + 1];
__device__ __align__(256) int    g_cursor[NN];
__device__ __align__(256) int    g_colsrc[EE];
__device__ __align__(256) float  g_h0[NN * HH];
__device__ __align__(256) float  g_h1[NN * HH];
__device__ __align__(256) __half g_h016[NN * HH];
__device__ __align__(256) __half g_h116[NN * HH];
__device__ __align__(256) __half g_decin16[NN * DD];
__device__ __align__(256) __half g_x16[TT * NN * FF];
// per-pipeline scratch (A = layer1, B = layer2)
__device__ __align__(256) __half g_hrzA[NN * 2 * HH];
__device__ __align__(256) __half g_hrzB[NN * 2 * HH];
__device__ __align__(256) __half g_hcA[NN * HH];
__device__ __align__(256) __half g_hcB[NN * HH];
__device__ __align__(256) float  g_el2A[NN * 2];
__device__ __align__(256) float  g_el2B[NN * 2];
__device__ __align__(256) float  g_er2A[NN * 2];
__device__ __align__(256) float  g_er2B[NN * 2];
__device__ __align__(256) float  g_el0A[NN];
__device__ __align__(256) float  g_el0B[NN];
__device__ __align__(256) float  g_er0A[NN];
__device__ __align__(256) float  g_er0B[NN];
__device__ __align__(256) float  g_zbufA[NN * HH];
__device__ __align__(256) float  g_zbufB[NN * HH];
__device__ __align__(256) __half g_rh16A[NN * HH];
__device__ __align__(256) __half g_rh16B[NN * HH];
// pre-converted fp16 weights, transposed [col][kpad], zero-padded
__device__ __align__(256) __half g_We0rz[128 * 80];
__device__ __align__(256) __half g_We0c[64 * 80];
__device__ __align__(256) __half g_We1rz[128 * 128];
__device__ __align__(256) __half g_We1c[64 * 128];
__device__ __align__(256) __half g_Wd0rz[128 * 80];
__device__ __align__(256) __half g_Wd0c[64 * 80];
__device__ __align__(256) __half g_Wd1rz[128 * 128];
__device__ __align__(256) __half g_Wd1c[64 * 128];

// ---------------- weight conversion helper ----------------
__device__ void convW_one(const float* W, __half* Wrz, __half* Wc,
                          int fin, int kpad, int idx) {
    int c = idx / kpad, k = idx - c * kpad;
    int g = c >> 6, ci = c & 63;
    float v = (k < fin) ? W[(size_t)(g * fin + k) * 64 + ci] : 0.f;
    __half hv = __float2half(v);
    if (g < 2) Wrz[c * kpad + k] = hv;
    else Wc[(c - 128) * kpad + k] = hv;
}

// ---------------- mega setup kernel: zero + x-conv + W-conv + degree hist ----------
__global__ void k_setup(const float* __restrict__ x, const int* __restrict__ dst,
                        const float* W0, const float* W1, const float* W2,
                        const float* W3,
                        __half* e0rz, __half* e0c, __half* e1rz, __half* e1c,
                        __half* d0rz, __half* d0c, __half* d1rz, __half* d1c,
                        float* h0, __half* h016, float* h1, __half* h116,
                        __half* decin16, __half* x16) {
    const int stride = gridDim.x * blockDim.x;
    int t0 = blockIdx.x * blockDim.x + threadIdx.x;
    for (int i = t0; i < NN * HH; i += stride) {
        h0[i] = 0.f; h1[i] = 0.f;
        h016[i] = __float2half(0.f); h116[i] = __float2half(0.f);
    }
    for (int i = t0; i < NN * DD; i += stride) decin16[i] = __float2half(0.f);
    for (int i = t0; i < TT * NN * FF; i += stride) x16[i] = __float2half(x[i]);
    const int S0 = 192 * 80, S1 = 192 * 128;
    for (int i = t0; i < 2 * S0 + 2 * S1; i += stride) {
        if (i < S0) convW_one(W0, e0rz, e0c, 66, 80, i);
        else if (i < S0 + S1) convW_one(W1, e1rz, e1c, 128, 128, i - S0);
        else if (i < 2 * S0 + S1) convW_one(W2, d0rz, d0c, 66, 80, i - S0 - S1);
        else convW_one(W3, d1rz, d1c, 128, 128, i - 2 * S0 - S1);
    }
    for (int e = t0; e < EE; e += stride) atomicAdd(&g_deg[dst[e]], 1);
}

__global__ void k_zero_i(int* p, int n) {
    int i = blockIdx.x * blockDim.x + threadIdx.x;
    if (i < n) p[i] = 0;
}

__global__ void k_scan() {
    __shared__ int part[1024];
    const int t = threadIdx.x;
    const int CH = (NN + 1023) / 1024;
    int beg = t * CH;
    int end = beg + CH; if (end > NN) end = NN;
    int s = 0;
    for (int i = beg; i < end; i++) s += g_deg[i];
    part[t] = s;
    __syncthreads();
    for (int off = 1; off < 1024; off <<= 1) {
        int v = (t >= off) ? part[t - off] : 0;
        __syncthreads();
        part[t] += v;
        __syncthreads();
    }
    int ex = (t == 0) ? 0 : part[t - 1];
    for (int i = beg; i < end; i++) {
        g_rowptr[i] = ex;
        g_cursor[i] = ex;
        ex += g_deg[i];
    }
    if (t == 0) g_rowptr[NN] = part[1023];
}

// ---------------- MMA / LDSM helpers ----------------
__device__ __forceinline__ void mma16816(float* d, const unsigned* a, const unsigned* b) {
    asm volatile(
        "mma.sync.aligned.m16n8k16.row.col.f32.f16.f16.f32 "
        "{%0,%1,%2,%3}, {%4,%5,%6,%7}, {%8,%9}, {%0,%1,%2,%3};\n"
        : "+f"(d[0]), "+f"(d[1]), "+f"(d[2]), "+f"(d[3])
        : "r"(a[0]), "r"(a[1]), "r"(a[2]), "r"(a[3]), "r"(b[0]), "r"(b[1]));
}
__device__ __forceinline__ void ldsm_x4(unsigned* r, unsigned addr) {
    asm volatile("ldmatrix.sync.aligned.m8n8.x4.shared.b16 {%0,%1,%2,%3}, [%4];"
                 : "=r"(r[0]), "=r"(r[1]), "=r"(r[2]), "=r"(r[3]) : "r"(addr));
}

// ---------------- GAT linear body (HMMA, 64-row tiles) ----------------
template <int NG, int KPAD, int FA>
__device__ __forceinline__
void gemm_body(int bid,
               const __half* __restrict__ featA, const __half* __restrict__ featH,
               const __half* __restrict__ Wt,
               const float* __restrict__ al, const float* __restrict__ ar,
               __half* __restrict__ hout,
               float* __restrict__ elp, float* __restrict__ erp) {
    constexpr int N = NG * 64;
    constexpr int NTH = (NG == 2) ? 256 : 128;
    constexpr int WST = KPAD + 8;
    constexpr int FST = KPAD + 8;
    extern __shared__ __half smh[];
    __half* Wsh = smh;             // [N][WST]
    __half* fsh = smh + N * WST;   // [64][FST]

    const int tid = threadIdx.x;
    const int lane = tid & 31;
    const int w = tid >> 5;
    const int row0 = bid * 64;

    {
        constexpr int QW = KPAD / 8;
        for (int idx = tid; idx < N * QW; idx += NTH) {
            int c = idx / QW, q = idx - c * QW;
            *(uint4*)(Wsh + c * WST + q * 8) = *(const uint4*)(Wt + c * KPAD + q * 8);
        }
    }
    if (FA == 2) {
        constexpr int C2 = KPAD / 2;
        for (int idx = tid; idx < 64 * C2; idx += NTH) {
            int r = idx / C2, c2 = idx - r * C2;
            int grow = row0 + r;
            __half2 v = __float2half2_rn(0.f);
            if (grow < NN) {
                if (c2 == 0) v = *(const __half2*)(featA + grow * 2);
                else if (c2 < 33) v = *(const __half2*)(featH + grow * 64 + (c2 - 1) * 2);
            }
            *(__half2*)(fsh + r * FST + c2 * 2) = v;
        }
    } else {
        for (int idx = tid; idx < 64 * 16; idx += NTH) {
            int r = idx >> 4, q = idx & 15;
            int grow = row0 + r;
            uint4 v = make_uint4(0, 0, 0, 0);
            if (grow < NN)
                v = (q < 8) ? *(const uint4*)(featA + (size_t)grow * 64 + q * 8)
                            : *(const uint4*)(featH + (size_t)grow * 64 + (q - 8) * 8);
            *(uint4*)(fsh + r * FST + q * 8) = v;
        }
    }
    __syncthreads();

    const int wm = (NG == 2) ? (w & 3) : w;
    const int wn = (NG == 2) ? (w >> 2) : 0;
    const int rbase = wm * 16;
    const int cbase = wn * 64;
    const int qr = lane >> 2;
    const int qc = lane & 3;

    float acc[8][4];
#pragma unroll
    for (int nf = 0; nf < 8; nf++)
#pragma unroll
        for (int p = 0; p < 4; p++) acc[nf][p] = 0.f;

    unsigned abase, bbase[4];
    abase = (unsigned)__cvta_generic_to_shared(
        fsh + (rbase + (lane & 15)) * FST + (lane >> 4) * 8);
#pragma unroll
    for (int p = 0; p < 4; p++)
        bbase[p] = (unsigned)__cvta_generic_to_shared(
            Wsh + (cbase + p * 16 + (lane & 15)) * WST + (lane >> 4) * 8);

#pragma unroll
    for (int k0 = 0; k0 < KPAD; k0 += 16) {
        unsigned a[4], bmat[4][4];
        ldsm_x4(a, abase + k0 * 2);
#pragma unroll
        for (int p = 0; p < 4; p++) ldsm_x4(bmat[p], bbase[p] + k0 * 2);
#pragma unroll
        for (int nf = 0; nf < 8; nf++) {
            unsigned b2[2];
            b2[0] = bmat[nf >> 1][(nf & 1) ? 1 : 0];
            b2[1] = bmat[nf >> 1][(nf & 1) ? 3 : 2];
            mma16816(acc[nf], a, b2);
        }
    }

    const float* alg = al + wn * 64;
    const float* arg = ar + wn * 64;
    {
        int grow0 = row0 + rbase + qr;
        int grow1 = grow0 + 8;
        float pe0 = 0.f, pr0 = 0.f, pe1 = 0.f, pr1 = 0.f;
#pragma unroll
        for (int nf = 0; nf < 8; nf++) {
            int cl = nf * 8 + qc * 2;
            float al0 = alg[cl], al1 = alg[cl + 1];
            float ar0 = arg[cl], ar1 = arg[cl + 1];
            pe0 += acc[nf][0] * al0 + acc[nf][1] * al1;
            pr0 += acc[nf][0] * ar0 + acc[nf][1] * ar1;
            pe1 += acc[nf][2] * al0 + acc[nf][3] * al1;
            pr1 += acc[nf][2] * ar0 + acc[nf][3] * ar1;
        }
#pragma unroll
        for (int off = 1; off < 4; off <<= 1) {
            pe0 += __shfl_xor_sync(0xffffffffu, pe0, off);
            pr0 += __shfl_xor_sync(0xffffffffu, pr0, off);
            pe1 += __shfl_xor_sync(0xffffffffu, pe1, off);
            pr1 += __shfl_xor_sync(0xffffffffu, pr1, off);
        }
        if (qc == 0) {
            if (grow0 < NN) { elp[grow0 * NG + wn] = pe0; erp[grow0 * NG + wn] = pr0; }
            if (grow1 < NN) { elp[grow1 * NG + wn] = pe1; erp[grow1 * NG + wn] = pr1; }
        }
#pragma unroll
        for (int nf = 0; nf < 8; nf++) {
            int gc = cbase + nf * 8 + qc * 2;
            if (grow0 < NN)
                *(__half2*)(hout + (size_t)grow0 * N + gc) =
                    __floats2half2_rn(acc[nf][0], acc[nf][1]);
            if (grow1 < NN)
                *(__half2*)(hout + (size_t)grow1 * N + gc) =
                    __floats2half2_rn(acc[nf][2], acc[nf][3]);
        }
    }
}

template <int NG, int KPAD, int FA>
__global__ __launch_bounds__(NG == 2 ? 256 : 128, NG == 2 ? 3 : 5)
void gemm_gat(const __half* __restrict__ featA, const __half* __restrict__ featH,
              const __half* __restrict__ Wt,
              const float* __restrict__ al, const float* __restrict__ ar,
              __half* __restrict__ hout,
              float* __restrict__ elp, float* __restrict__ erp) {
    gemm_body<NG, KPAD, FA>(blockIdx.x, featA, featH, Wt, al, ar, hout, elp, erp);
}

// ---------------- combined CSR scatter + t=0 layer-1 r/z GEMM ----------------
static const int SCAT_BLKS = (EE + 255) / 256;   // 3125
__global__ __launch_bounds__(256, 3)
void k_scatter_gemm(const int* __restrict__ src, const int* __restrict__ dst,
                    const __half* __restrict__ featA, const __half* __restrict__ featH,
                    const __half* __restrict__ Wt,
                    const float* __restrict__ al, const float* __restrict__ ar,
                    __half* __restrict__ hout,
                    float* __restrict__ elp, float* __restrict__ erp) {
    if (blockIdx.x < SCAT_BLKS) {
        int e = blockIdx.x * 256 + threadIdx.x;
        if (e < EE) {
            int d = dst[e];
            int pos = atomicAdd(&g_cursor[d], 1);
            g_colsrc[pos] = src[e];
        }
        return;
    }
    gemm_body<2, 80, 2>(blockIdx.x - SCAT_BLKS, featA, featH, Wt, al, ar,
                        hout, elp, erp);
}

// ---------------- r/z aggregation + fused GRU gate elementwise ----------------
// 2 edges per step: lanes 0-15 process even-step edge, lanes 16-31 odd-step edge.
// Each lane covers 8 columns (sub*8..+7) via one LDG.128; cols sub<8 = r gate,
// sub>=8 = z gate. Weight gathering: lane l computes gate (l>>4)'s weight for
// edge (l&15); consumer selects src lane = (col-gate)*16 + edge.
__global__ void agg_rz(const __half* __restrict__ h,
                       const float2* __restrict__ el2, const float2* __restrict__ er2,
                       const float* __restrict__ b,
                       const float* __restrict__ hx,
                       __half* __restrict__ rh16, float* __restrict__ zbuf) {
    int wid = (blockIdx.x * blockDim.x + threadIdx.x) >> 5;
    if (wid >= NN) return;
    const int lane = threadIdx.x & 31;
    const int sub = lane & 15;
    const int half = lane >> 4;          // my step-parity AND my weight-gate
    const int gsel = sub >> 3;           // gate of my 8 columns (0=r, 1=z)
    const int beg = g_rowptr[wid];
    const int end = g_rowptr[wid + 1];
    const float2 er = er2[wid];
    const float erd = half ? er.y : er.x;

    float wsum = 0.f;
    float f[8];
#pragma unroll
    for (int p = 0; p < 8; p++) f[p] = 0.f;

    for (int j0 = beg; j0 < end; j0 += 16) {
        int jj = j0 + sub;
        int sv = 0;
        float wv = 0.f;
        if (jj < end) {
            sv = g_colsrc[jj];
            float2 ev = el2[sv];
            float e = (half ? ev.y : ev.x) + erd;
            e = e > 0.f ? e : 0.2f * e;
            wv = __expf(e);
        }
        wsum += wv;
        int cnt = end - j0; if (cnt > 16) cnt = 16;
#pragma unroll 4
        for (int i = 0; i < cnt; i += 2) {
            int eidx = i + half;                 // my edge this step (may be == cnt: w=0)
            int s = __shfl_sync(0xffffffffu, sv, eidx);
            float wgt = __shfl_sync(0xffffffffu, wv, gsel * 16 + eidx);
            uint4 u = *(const uint4*)(h + (size_t)s * 128 + sub * 8);
            float2 v0 = __half22float2(*(__half2*)&u.x);
            float2 v1 = __half22float2(*(__half2*)&u.y);
            float2 v2 = __half22float2(*(__half2*)&u.z);
            float2 v3 = __half22float2(*(__half2*)&u.w);
            f[0] = fmaf(wgt, v0.x, f[0]);
            f[1] = fmaf(wgt, v0.y, f[1]);
            f[2] = fmaf(wgt, v1.x, f[2]);
            f[3] = fmaf(wgt, v1.y, f[3]);
            f[4] = fmaf(wgt, v2.x, f[4]);
            f[5] = fmaf(wgt, v2.y, f[5]);
            f[6] = fmaf(wgt, v3.x, f[6]);
            f[7] = fmaf(wgt, v3.y, f[7]);
        }
    }

    // combine the two edge-halves (lanes l and l^16 hold the same columns)
#pragma unroll
    for (int p = 0; p < 8; p++) f[p] += __shfl_xor_sync(0xffffffffu, f[p], 16);
    // per-gate weight sums (lane's wsum belongs to gate `half`)
#pragma unroll
    for (int off = 1; off < 16; off <<= 1)
        wsum += __shfl_xor_sync(0xffffffffu, wsum, off);
    float wden = __shfl_sync(0xffffffffu, wsum, gsel * 16);

    if (half == 0) {
        float inv = 1.f / fmaxf(wden, 1e-9f);
        const int col8 = sub * 8;
        float g[8];
#pragma unroll
        for (int p = 0; p < 8; p++)
            g[p] = 1.f / (1.f + __expf(-(f[p] * inv + b[col8 + p])));
        if (gsel == 0) {
            // r gate: rh = g * hx, fp16
            float4 hv0 = *(const float4*)(hx + (size_t)wid * 64 + col8);
            float4 hv1 = *(const float4*)(hx + (size_t)wid * 64 + col8 + 4);
            __half2 r0 = __floats2half2_rn(g[0] * hv0.x, g[1] * hv0.y);
            __half2 r1 = __floats2half2_rn(g[2] * hv0.z, g[3] * hv0.w);
            __half2 r2 = __floats2half2_rn(g[4] * hv1.x, g[5] * hv1.y);
            __half2 r3 = __floats2half2_rn(g[6] * hv1.z, g[7] * hv1.w);
            uint4 st;
            st.x = *(unsigned*)&r0;
            st.y = *(unsigned*)&r1;
            st.z = *(unsigned*)&r2;
            st.w = *(unsigned*)&r3;
            *(uint4*)(rh16 + (size_t)wid * 64 + col8) = st;
        } else {
            // z gate: zbuf fp32 (z cols are col8-64 .. +7)
            int zc = col8 - 64;
            *(float4*)(zbuf + (size_t)wid * 64 + zc) =
                make_float4(g[0], g[1], g[2], g[3]);
            *(float4*)(zbuf + (size_t)wid * 64 + zc + 4) =
                make_float4(g[4], g[5], g[6], g[7]);
        }
    }
}

// ---------------- candidate aggregation + fused GRU update (+ optional proj) --------
// 2 edges per step; lane covers 4 cols (sub*4..+3) via LDG.64. Batch = 32 edges,
// each lane computes one edge's weight.
template <bool PROJ>
__global__ void agg_c(const __half* __restrict__ h,
                      const float* __restrict__ el, const float* __restrict__ er,
                      const float* __restrict__ b2,
                      const float* __restrict__ zbuf,
                      float* __restrict__ hx, __half* __restrict__ hx16,
                      const float* __restrict__ pW, const float* __restrict__ pb,
                      float* __restrict__ outslice, __half* __restrict__ decin16) {
    int wid = (blockIdx.x * blockDim.x + threadIdx.x) >> 5;
    if (wid >= NN) return;
    const int lane = threadIdx.x & 31;
    const int sub = lane & 15;
    const int half = lane >> 4;
    const int beg = g_rowptr[wid];
    const int end = g_rowptr[wid + 1];
    const float erd = er[wid];

    float wsum = 0.f;
    float f[4];
#pragma unroll
    for (int p = 0; p < 4; p++) f[p] = 0.f;

    for (int j0 = beg; j0 < end; j0 += 32) {
        int jj = j0 + lane;
        int sv = 0;
        float wv = 0.f;
        if (jj < end) {
            sv = g_colsrc[jj];
            float e = el[sv] + erd; e = e > 0.f ? e : 0.2f * e;
            wv = __expf(e);
        }
        wsum += wv;
        int cnt = end - j0; if (cnt > 32) cnt = 32;
#pragma unroll 4
        for (int i = 0; i < cnt; i += 2) {
            int eidx = i + half;
            int s = __shfl_sync(0xffffffffu, sv, eidx);
            float wgt = __shfl_sync(0xffffffffu, wv, eidx);
            uint2 u = *(const uint2*)(h + (size_t)s * 64 + sub * 4);
            float2 v0 = __half22float2(*(__half2*)&u.x);
            float2 v1 = __half22float2(*(__half2*)&u.y);
            f[0] = fmaf(wgt, v0.x, f[0]);
            f[1] = fmaf(wgt, v0.y, f[1]);
            f[2] = fmaf(wgt, v1.x, f[2]);
            f[3] = fmaf(wgt, v1.y, f[3]);
        }
    }

#pragma unroll
    for (int p = 0; p < 4; p++) f[p] += __shfl_xor_sync(0xffffffffu, f[p], 16);
#pragma unroll
    for (int off = 1; off < 32; off <<= 1)
        wsum += __shfl_xor_sync(0xffffffffu, wsum, off);

    float n[4];
    if (half == 0) {
        float inv = 1.f / fmaxf(wsum, 1e-9f);
        const int c4 = sub * 4;
        float4 z = *(const float4*)(zbuf + (size_t)wid * 64 + c4);
        float4 hv = *(const float4*)(hx + (size_t)wid * 64 + c4);
        float hc0 = tanhf(f[0] * inv + b2[c4]);
        float hc1 = tanhf(f[1] * inv + b2[c4 + 1]);
        float hc2 = tanhf(f[2] * inv + b2[c4 + 2]);
        float hc3 = tanhf(f[3] * inv + b2[c4 + 3]);
        n[0] = z.x * hv.x + (1.f - z.x) * hc0;
        n[1] = z.y * hv.y + (1.f - z.y) * hc1;
        n[2] = z.z * hv.z + (1.f - z.z) * hc2;
        n[3] = z.w * hv.w + (1.f - z.w) * hc3;
        *(float4*)(hx + (size_t)wid * 64 + c4) = make_float4(n[0], n[1], n[2], n[3]);
        __half2 h01 = __floats2half2_rn(n[0], n[1]);
        __half2 h23 = __floats2half2_rn(n[2], n[3]);
        uint2 st;
        st.x = *(unsigned*)&h01;
        st.y = *(unsigned*)&h23;
        *(uint2*)(hx16 + (size_t)wid * 64 + c4) = st;
    }

    if (PROJ) {
        float o0 = 0.f, o1 = 0.f;
        if (half == 0) {
            const int c4 = sub * 4;
#pragma unroll
            for (int k = 0; k < 4; k++) {
                o0 += n[k] * pW[2 * (c4 + k)];
                o1 += n[k] * pW[2 * (c4 + k) + 1];
            }
        }
#pragma unroll
        for (int off = 1; off < 16; off <<= 1) {
            o0 += __shfl_xor_sync(0xffffffffu, o0, off);
            o1 += __shfl_xor_sync(0xffffffffu, o1, off);
        }
        if (lane == 0) {
            o0 += pb[0];
            o1 += pb[1];
            outslice[2 * wid] = o0;
            outslice[2 * wid + 1] = o1;
            *(__half2*)(decin16 + (size_t)wid * 2) = __floats2half2_rn(o0, o1);
        }
    }
}

// ---------------- host orchestration ----------------
struct Scr {
    __half *hrz, *hc, *rh16;
    float *el2, *er2, *el0, *er0, *zbuf;
};
struct DevPtrs {
    int *deg, *rowptr, *cursor, *colsrc;
    float *h0, *h1;
    __half *h016, *h116, *decin16, *x16;
    Scr A, B;
    __half *We0rz, *We0c, *We1rz, *We1c, *Wd0rz, *Wd0c, *Wd1rz, *Wd1c;
};

static void get_ptrs(DevPtrs& P) {
    cudaGetSymbolAddress((void**)&P.deg, g_deg);
    cudaGetSymbolAddress((void**)&P.rowptr, g_rowptr);
    cudaGetSymbolAddress((void**)&P.cursor, g_cursor);
    cudaGetSymbolAddress((void**)&P.colsrc, g_colsrc);
    cudaGetSymbolAddress((void**)&P.h0, g_h0);
    cudaGetSymbolAddress((void**)&P.h1, g_h1);
    cudaGetSymbolAddress((void**)&P.h016, g_h016);
    cudaGetSymbolAddress((void**)&P.h116, g_h116);
    cudaGetSymbolAddress((void**)&P.decin16, g_decin16);
    cudaGetSymbolAddress((void**)&P.x16, g_x16);
    cudaGetSymbolAddress((void**)&P.A.hrz, g_hrzA);
    cudaGetSymbolAddress((void**)&P.A.hc, g_hcA);
    cudaGetSymbolAddress((void**)&P.A.rh16, g_rh16A);
    cudaGetSymbolAddress((void**)&P.A.el2, g_el2A);
    cudaGetSymbolAddress((void**)&P.A.er2, g_er2A);
    cudaGetSymbolAddress((void**)&P.A.el0, g_el0A);
    cudaGetSymbolAddress((void**)&P.A.er0, g_er0A);
    cudaGetSymbolAddress((void**)&P.A.zbuf, g_zbufA);
    cudaGetSymbolAddress((void**)&P.B.hrz, g_hrzB);
    cudaGetSymbolAddress((void**)&P.B.hc, g_hcB);
    cudaGetSymbolAddress((void**)&P.B.rh16, g_rh16B);
    cudaGetSymbolAddress((void**)&P.B.el2, g_el2B);
    cudaGetSymbolAddress((void**)&P.B.er2, g_er2B);
    cudaGetSymbolAddress((void**)&P.B.el0, g_el0B);
    cudaGetSymbolAddress((void**)&P.B.er0, g_er0B);
    cudaGetSymbolAddress((void**)&P.B.zbuf, g_zbufB);
    cudaGetSymbolAddress((void**)&P.We0rz, g_We0rz);
    cudaGetSymbolAddress((void**)&P.We0c, g_We0c);
    cudaGetSymbolAddress((void**)&P.We1rz, g_We1rz);
    cudaGetSymbolAddress((void**)&P.We1c, g_We1c);
    cudaGetSymbolAddress((void**)&P.Wd0rz, g_Wd0rz);
    cudaGetSymbolAddress((void**)&P.Wd0c, g_Wd0c);
    cudaGetSymbolAddress((void**)&P.Wd1rz, g_Wd1rz);
    cudaGetSymbolAddress((void**)&P.Wd1c, g_Wd1c);
}

static const int GEMM_BLKS = (NN + 63) / 64;   // 782
static const int AGG_BLKS = (NN + 7) / 8;
#define SMEM_SZ(NG_, KP_) ((size_t)((NG_) * 64 + 64) * ((KP_) + 8) * sizeof(__half))

static void L_gemm2_l1(cudaStream_t st, const Scr& S,
                       const __half* fa, const __half* fh, const __half* Wrz,
                       const float* al, const float* ar) {
    gemm_gat<2, 80, 2><<<GEMM_BLKS, 256, SMEM_SZ(2, 80), st>>>(
        fa, fh, Wrz, al, ar, S.hrz, S.el2, S.er2);
}
static void L_gemm1_l1(cudaStream_t st, const Scr& S,
                       const __half* fa, const __half* Wc,
                       const float* al, const float* ar) {
    gemm_gat<1, 80, 2><<<GEMM_BLKS, 128, SMEM_SZ(1, 80), st>>>(
        fa, S.rh16, Wc, al + 128, ar + 128, S.hc, S.el0, S.er0);
}
static void L_gemm2_l2(cudaStream_t st, const Scr& S,
                       const __half* fa, const __half* fh, const __half* Wrz,
                       const float* al, const float* ar) {
    gemm_gat<2, 128, 64><<<GEMM_BLKS, 256, SMEM_SZ(2, 128), st>>>(
        fa, fh, Wrz, al, ar, S.hrz, S.el2, S.er2);
}
static void L_gemm1_l2(cudaStream_t st, const Scr& S,
                       const __half* fa, const __half* Wc,
                       const float* al, const float* ar) {
    gemm_gat<1, 128, 64><<<GEMM_BLKS, 128, SMEM_SZ(1, 128), st>>>(
        fa, S.rh16, Wc, al + 128, ar + 128, S.hc, S.el0, S.er0);
}
static void L_aggrz(cudaStream_t st, const Scr& S, const float* b, const float* hx) {
    agg_rz<<<AGG_BLKS, 256, 0, st>>>(S.hrz, (const float2*)S.el2,
                                     (const float2*)S.er2, b, hx, S.rh16, S.zbuf);
}
static void L_aggc(cudaStream_t st, const DevPtrs& P, const Scr& S, const float* b,
                   float* hx, __half* hx16,
                   const float* pW = nullptr, const float* pb = nullptr,
                   float* outslice = nullptr) {
    if (outslice)
        agg_c<true><<<AGG_BLKS, 256, 0, st>>>(S.hc, S.el0, S.er0,
                                              b + 128, S.zbuf, hx, hx16, pW, pb,
                                              outslice, P.decin16);
    else
        agg_c<false><<<AGG_BLKS, 256, 0, st>>>(S.hc, S.el0, S.er0,
                                               b + 128, S.zbuf, hx, hx16,
                                               nullptr, nullptr, nullptr, nullptr);
}

extern "C" void kernel_launch(void* const* d_in, const int* in_sizes, int n_in,
                              void* d_out, int out_size) {
    (void)in_sizes; (void)n_in;
    const float* x = (const float*)d_in[0];
    const int* src = (const int*)d_in[1];
    const int* dst = (const int*)d_in[2];
    const float* enc_W0 = (const float*)d_in[3];
    const float* enc_al0 = (const float*)d_in[4];
    const float* enc_ar0 = (const float*)d_in[5];
    const float* enc_b0 = (const float*)d_in[6];
    const float* enc_W1 = (const float*)d_in[7];
    const float* enc_al1 = (const float*)d_in[8];
    const float* enc_ar1 = (const float*)d_in[9];
    const float* enc_b1 = (const float*)d_in[10];
    const float* dec_W0 = (const float*)d_in[11];
    const float* dec_al0 = (const float*)d_in[12];
    const float* dec_ar0 = (const float*)d_in[13];
    const float* dec_b0 = (const float*)d_in[14];
    const float* dec_W1 = (const float*)d_in[15];
    const float* dec_al1 = (const float*)d_in[16];
    const float* dec_ar1 = (const float*)d_in[17];
    const float* dec_b1 = (const float*)d_in[18];
    const float* proj_W = (const float*)d_in[19];
    const float* proj_b = (const float*)d_in[20];
    float* out = (float*)d_out;
    (void)out_size;

    static cudaStream_t s2 = nullptr;
    static cudaEvent_t ev1 = nullptr, ev2 = nullptr, ev3 = nullptr;
    if (!s2) {
        cudaStreamCreateWithFlags(&s2, cudaStreamNonBlocking);
        cudaEventCreateWithFlags(&ev1, cudaEventDisableTiming);
        cudaEventCreateWithFlags(&ev2, cudaEventDisableTiming);
        cudaEventCreateWithFlags(&ev3, cudaEventDisableTiming);
        cudaFuncSetAttribute((const void*)gemm_gat<2, 128, 64>,
                             cudaFuncAttributeMaxDynamicSharedMemorySize, 54 * 1024);
        cudaFuncSetAttribute((const void*)gemm_gat<1, 128, 64>,
                             cudaFuncAttributeMaxDynamicSharedMemorySize, 36 * 1024);
    }

    DevPtrs P;
    get_ptrs(P);
    cudaStream_t s0 = 0;

    // --- setup: 3 launches; launch #4 is agg_rz (profiled by ncu) ---
    k_setup<<<2048, 256, 0, s0>>>(x, dst, enc_W0, enc_W1, dec_W0, dec_W1,        // 1
                                  P.We0rz, P.We0c, P.We1rz, P.We1c,
                                  P.Wd0rz, P.Wd0c, P.Wd1rz, P.Wd1c,
                                  P.h0, P.h016, P.h1, P.h116, P.decin16, P.x16);
    k_scan<<<1, 1024, 0, s0>>>();                                                // 2
    k_scatter_gemm<<<SCAT_BLKS + GEMM_BLKS, 256, SMEM_SZ(2, 80), s0>>>(          // 3
        src, dst, P.x16, P.h016, P.We0rz, enc_al0, enc_ar0,
        P.A.hrz, P.A.el2, P.A.er2);

    // --- encoder t=0, layer 1 ---
    L_aggrz(s0, P.A, enc_b0, P.h0);                                              // 4 (profiled)
    L_gemm1_l1(s0, P.A, P.x16, P.We0c, enc_al0, enc_ar0);
    L_aggc(s0, P, P.A, enc_b0, P.h0, P.h016);
    cudaEventRecord(ev1, s0);

    // layer 2 t=0 on s2
    cudaStreamWaitEvent(s2, ev1, 0);
    L_gemm2_l2(s2, P.B, P.h016, P.h116, P.We1rz, enc_al1, enc_ar1);
    L_aggrz(s2, P.B, enc_b1, P.h1);
    L_gemm1_l2(s2, P.B, P.h016, P.We1c, enc_al1, enc_ar1);
    cudaEventRecord(ev2, s2);                   // last h016 read by layer2(t)
    L_aggc(s2, P, P.B, enc_b1, P.h1, P.h116);

    for (int t = 1; t < TT; t++) {
        const __half* xt = P.x16 + (size_t)t * NN * FF;
        L_gemm2_l1(s0, P.A, xt, P.h016, P.We0rz, enc_al0, enc_ar0);
        L_aggrz(s0, P.A, enc_b0, P.h0);
        L_gemm1_l1(s0, P.A, xt, P.We0c, enc_al0, enc_ar0);
        cudaStreamWaitEvent(s0, ev2, 0);        // layer2(t-1) done reading h016
        L_aggc(s0, P, P.A, enc_b0, P.h0, P.h016);
        cudaEventRecord(ev1, s0);
        cudaStreamWaitEvent(s2, ev1, 0);
        L_gemm2_l2(s2, P.B, P.h016, P.h116, P.We1rz, enc_al1, enc_ar1);
        L_aggrz(s2, P.B, enc_b1, P.h1);
        L_gemm1_l2(s2, P.B, P.h016, P.We1c, enc_al1, enc_ar1);
        cudaEventRecord(ev2, s2);
        L_aggc(s2, P, P.B, enc_b1, P.h1, P.h116);
    }

    cudaEventRecord(ev3, s2);
    cudaStreamWaitEvent(s0, ev3, 0);

    // --- decoder (serial on s0) ---
    for (int t = 0; t < HZ; t++) {
        L_gemm2_l1(s0, P.A, P.decin16, P.h016, P.Wd0rz, dec_al0, dec_ar0);
        L_aggrz(s0, P.A, dec_b0, P.h0);
        L_gemm1_l1(s0, P.A, P.decin16, P.Wd0c, dec_al0, dec_ar0);
        L_aggc(s0, P, P.A, dec_b0, P.h0, P.h016);
        L_gemm2_l2(s0, P.B, P.h016, P.h116, P.Wd1rz, dec_al1, dec_ar1);
        L_aggrz(s0, P.B, dec_b1, P.h1);
        L_gemm1_l2(s0, P.B, P.h016, P.Wd1c, dec_al1, dec_ar1);
        L_aggc(s0, P, P.B, dec_b1, P.h1, P.h116, proj_W, proj_b,
               out + (size_t)t * NN * DD);
    }

    // re-zero degree histogram for the next replay (stream-ordered after k_scan)
    k_zero_i<<<(NN + 255) / 256, 256, 0, s0>>>(P.deg, NN);
}

// round 14
// speedup vs baseline: 1.0829x; 1.0829x over previous
#include <cuda_runtime.h>
#include <cuda_fp16.h>
#include <math.h>

// Problem constants
#define NN 50000
#define EE 800000
#define FF 2
#define DD 2
#define HH 64
#define TT 12
#define HZ 12

// ---------------- scratch (static device globals; no allocation) ----------------
__device__ __align__(256) int    g_deg[NN];        // zeroed at end of each launch
__device__ __align__(256) int    g_rowptr[NN + 1];
__device__ __align__(256) int    g_cursor[NN];
__device__ __align__(256) int    g_colsrc[EE];
__device__ __align__(256) float  g_h0[NN * HH];
__device__ __align__(256) float  g_h1[NN * HH];
__device__ __align__(256) __half g_h016[NN * HH];
__device__ __align__(256) __half g_h116[NN * HH];
__device__ __align__(256) __half g_decin16[NN * DD];
__device__ __align__(256) __half g_x16[TT * NN * FF];
// per-pipeline scratch (A = layer1, B = layer2)
__device__ __align__(256) __half g_hrzA[NN * 2 * HH];
__device__ __align__(256) __half g_hrzB[NN * 2 * HH];
__device__ __align__(256) __half g_hcA[NN * HH];
__device__ __align__(256) __half g_hcB[NN * HH];
__device__ __align__(256) float  g_el2A[NN * 2];
__device__ __align__(256) float  g_el2B[NN * 2];
__device__ __align__(256) float  g_er2A[NN * 2];
__device__ __align__(256) float  g_er2B[NN * 2];
__device__ __align__(256) float  g_el0A[NN];
__device__ __align__(256) float  g_el0B[NN];
__device__ __align__(256) float  g_er0A[NN];
__device__ __align__(256) float  g_er0B[NN];
__device__ __align__(256) float  g_zbufA[NN * HH];
__device__ __align__(256) float  g_zbufB[NN * HH];
__device__ __align__(256) __half g_rh16A[NN * HH];
__device__ __align__(256) __half g_rh16B[NN * HH];
// pre-converted fp16 weights, transposed [col][kpad], zero-padded
__device__ __align__(256) __half g_We0rz[128 * 80];
__device__ __align__(256) __half g_We0c[64 * 80];
__device__ __align__(256) __half g_We1rz[128 * 128];
__device__ __align__(256) __half g_We1c[64 * 128];
__device__ __align__(256) __half g_Wd0rz[128 * 80];
__device__ __align__(256) __half g_Wd0c[64 * 80];
__device__ __align__(256) __half g_Wd1rz[128 * 128];
__device__ __align__(256) __half g_Wd1c[64 * 128];

// ---------------- mixed-precision FMA helpers (sm_100: fma.rn.f32.f16) ----------
__device__ __forceinline__ void fmah(float& acc, unsigned short hv, unsigned short w16) {
    asm("fma.rn.f32.f16 %0, %1, %2, %0;" : "+f"(acc) : "h"(hv), "h"(w16));
}
__device__ __forceinline__ void fma4h(float* f, uint2 u, unsigned short w16) {
    fmah(f[0], (unsigned short)(u.x), w16);
    fmah(f[1], (unsigned short)(u.x >> 16), w16);
    fmah(f[2], (unsigned short)(u.y), w16);
    fmah(f[3], (unsigned short)(u.y >> 16), w16);
}

// ---------------- weight conversion helper ----------------
__device__ void convW_one(const float* W, __half* Wrz, __half* Wc,
                          int fin, int kpad, int idx) {
    int c = idx / kpad, k = idx - c * kpad;
    int g = c >> 6, ci = c & 63;
    float v = (k < fin) ? W[(size_t)(g * fin + k) * 64 + ci] : 0.f;
    __half hv = __float2half(v);
    if (g < 2) Wrz[c * kpad + k] = hv;
    else Wc[(c - 128) * kpad + k] = hv;
}

// ---------------- mega setup kernel: zero + x-conv + W-conv + degree hist ----------
__global__ void k_setup(const float* __restrict__ x, const int* __restrict__ dst,
                        const float* W0, const float* W1, const float* W2,
                        const float* W3,
                        __half* e0rz, __half* e0c, __half* e1rz, __half* e1c,
                        __half* d0rz, __half* d0c, __half* d1rz, __half* d1c,
                        float* h0, __half* h016, float* h1, __half* h116,
                        __half* decin16, __half* x16) {
    const int stride = gridDim.x * blockDim.x;
    int t0 = blockIdx.x * blockDim.x + threadIdx.x;
    for (int i = t0; i < NN * HH; i += stride) {
        h0[i] = 0.f; h1[i] = 0.f;
        h016[i] = __float2half(0.f); h116[i] = __float2half(0.f);
    }
    for (int i = t0; i < NN * DD; i += stride) decin16[i] = __float2half(0.f);
    for (int i = t0; i < TT * NN * FF; i += stride) x16[i] = __float2half(x[i]);
    const int S0 = 192 * 80, S1 = 192 * 128;
    for (int i = t0; i < 2 * S0 + 2 * S1; i += stride) {
        if (i < S0) convW_one(W0, e0rz, e0c, 66, 80, i);
        else if (i < S0 + S1) convW_one(W1, e1rz, e1c, 128, 128, i - S0);
        else if (i < 2 * S0 + S1) convW_one(W2, d0rz, d0c, 66, 80, i - S0 - S1);
        else convW_one(W3, d1rz, d1c, 128, 128, i - 2 * S0 - S1);
    }
    for (int e = t0; e < EE; e += stride) atomicAdd(&g_deg[dst[e]], 1);
}

__global__ void k_zero_i(int* p, int n) {
    int i = blockIdx.x * blockDim.x + threadIdx.x;
    if (i < n) p[i] = 0;
}

__global__ void k_scan() {
    __shared__ int part[1024];
    const int t = threadIdx.x;
    const int CH = (NN + 1023) / 1024;
    int beg = t * CH;
    int end = beg + CH; if (end > NN) end = NN;
    int s = 0;
    for (int i = beg; i < end; i++) s += g_deg[i];
    part[t] = s;
    __syncthreads();
    for (int off = 1; off < 1024; off <<= 1) {
        int v = (t >= off) ? part[t - off] : 0;
        __syncthreads();
        part[t] += v;
        __syncthreads();
    }
    int ex = (t == 0) ? 0 : part[t - 1];
    for (int i = beg; i < end; i++) {
        g_rowptr[i] = ex;
        g_cursor[i] = ex;
        ex += g_deg[i];
    }
    if (t == 0) g_rowptr[NN] = part[1023];
}

// ---------------- MMA / LDSM helpers ----------------
__device__ __forceinline__ void mma16816(float* d, const unsigned* a, const unsigned* b) {
    asm volatile(
        "mma.sync.aligned.m16n8k16.row.col.f32.f16.f16.f32 "
        "{%0,%1,%2,%3}, {%4,%5,%6,%7}, {%8,%9}, {%0,%1,%2,%3};\n"
        : "+f"(d[0]), "+f"(d[1]), "+f"(d[2]), "+f"(d[3])
        : "r"(a[0]), "r"(a[1]), "r"(a[2]), "r"(a[3]), "r"(b[0]), "r"(b[1]));
}
__device__ __forceinline__ void ldsm_x4(unsigned* r, unsigned addr) {
    asm volatile("ldmatrix.sync.aligned.m8n8.x4.shared.b16 {%0,%1,%2,%3}, [%4];"
                 : "=r"(r[0]), "=r"(r[1]), "=r"(r[2]), "=r"(r[3]) : "r"(addr));
}

// ---------------- GAT linear body (HMMA, 64-row tiles) ----------------
template <int NG, int KPAD, int FA>
__device__ __forceinline__
void gemm_body(int bid,
               const __half* __restrict__ featA, const __half* __restrict__ featH,
               const __half* __restrict__ Wt,
               const float* __restrict__ al, const float* __restrict__ ar,
               __half* __restrict__ hout,
               float* __restrict__ elp, float* __restrict__ erp) {
    constexpr int N = NG * 64;
    constexpr int NTH = (NG == 2) ? 256 : 128;
    constexpr int WST = KPAD + 8;
    constexpr int FST = KPAD + 8;
    extern __shared__ __half smh[];
    __half* Wsh = smh;             // [N][WST]
    __half* fsh = smh + N * WST;   // [64][FST]

    const int tid = threadIdx.x;
    const int lane = tid & 31;
    const int w = tid >> 5;
    const int row0 = bid * 64;

    {
        constexpr int QW = KPAD / 8;
        for (int idx = tid; idx < N * QW; idx += NTH) {
            int c = idx / QW, q = idx - c * QW;
            *(uint4*)(Wsh + c * WST + q * 8) = *(const uint4*)(Wt + c * KPAD + q * 8);
        }
    }
    if (FA == 2) {
        constexpr int C2 = KPAD / 2;
        for (int idx = tid; idx < 64 * C2; idx += NTH) {
            int r = idx / C2, c2 = idx - r * C2;
            int grow = row0 + r;
            __half2 v = __float2half2_rn(0.f);
            if (grow < NN) {
                if (c2 == 0) v = *(const __half2*)(featA + grow * 2);
                else if (c2 < 33) v = *(const __half2*)(featH + grow * 64 + (c2 - 1) * 2);
            }
            *(__half2*)(fsh + r * FST + c2 * 2) = v;
        }
    } else {
        for (int idx = tid; idx < 64 * 16; idx += NTH) {
            int r = idx >> 4, q = idx & 15;
            int grow = row0 + r;
            uint4 v = make_uint4(0, 0, 0, 0);
            if (grow < NN)
                v = (q < 8) ? *(const uint4*)(featA + (size_t)grow * 64 + q * 8)
                            : *(const uint4*)(featH + (size_t)grow * 64 + (q - 8) * 8);
            *(uint4*)(fsh + r * FST + q * 8) = v;
        }
    }
    __syncthreads();

    const int wm = (NG == 2) ? (w & 3) : w;
    const int wn = (NG == 2) ? (w >> 2) : 0;
    const int rbase = wm * 16;
    const int cbase = wn * 64;
    const int qr = lane >> 2;
    const int qc = lane & 3;

    float acc[8][4];
#pragma unroll
    for (int nf = 0; nf < 8; nf++)
#pragma unroll
        for (int p = 0; p < 4; p++) acc[nf][p] = 0.f;

    unsigned abase, bbase[4];
    abase = (unsigned)__cvta_generic_to_shared(
        fsh + (rbase + (lane & 15)) * FST + (lane >> 4) * 8);
#pragma unroll
    for (int p = 0; p < 4; p++)
        bbase[p] = (unsigned)__cvta_generic_to_shared(
            Wsh + (cbase + p * 16 + (lane & 15)) * WST + (lane >> 4) * 8);

#pragma unroll
    for (int k0 = 0; k0 < KPAD; k0 += 16) {
        unsigned a[4], bmat[4][4];
        ldsm_x4(a, abase + k0 * 2);
#pragma unroll
        for (int p = 0; p < 4; p++) ldsm_x4(bmat[p], bbase[p] + k0 * 2);
#pragma unroll
        for (int nf = 0; nf < 8; nf++) {
            unsigned b2[2];
            b2[0] = bmat[nf >> 1][(nf & 1) ? 1 : 0];
            b2[1] = bmat[nf >> 1][(nf & 1) ? 3 : 2];
            mma16816(acc[nf], a, b2);
        }
    }

    const float* alg = al + wn * 64;
    const float* arg = ar + wn * 64;
    {
        int grow0 = row0 + rbase + qr;
        int grow1 = grow0 + 8;
        float pe0 = 0.f, pr0 = 0.f, pe1 = 0.f, pr1 = 0.f;
#pragma unroll
        for (int nf = 0; nf < 8; nf++) {
            int cl = nf * 8 + qc * 2;
            float al0 = alg[cl], al1 = alg[cl + 1];
            float ar0 = arg[cl], ar1 = arg[cl + 1];
            pe0 += acc[nf][0] * al0 + acc[nf][1] * al1;
            pr0 += acc[nf][0] * ar0 + acc[nf][1] * ar1;
            pe1 += acc[nf][2] * al0 + acc[nf][3] * al1;
            pr1 += acc[nf][2] * ar0 + acc[nf][3] * ar1;
        }
#pragma unroll
        for (int off = 1; off < 4; off <<= 1) {
            pe0 += __shfl_xor_sync(0xffffffffu, pe0, off);
            pr0 += __shfl_xor_sync(0xffffffffu, pr0, off);
            pe1 += __shfl_xor_sync(0xffffffffu, pe1, off);
            pr1 += __shfl_xor_sync(0xffffffffu, pr1, off);
        }
        if (qc == 0) {
            if (grow0 < NN) { elp[grow0 * NG + wn] = pe0; erp[grow0 * NG + wn] = pr0; }
            if (grow1 < NN) { elp[grow1 * NG + wn] = pe1; erp[grow1 * NG + wn] = pr1; }
        }
#pragma unroll
        for (int nf = 0; nf < 8; nf++) {
            int gc = cbase + nf * 8 + qc * 2;
            if (grow0 < NN)
                *(__half2*)(hout + (size_t)grow0 * N + gc) =
                    __floats2half2_rn(acc[nf][0], acc[nf][1]);
            if (grow1 < NN)
                *(__half2*)(hout + (size_t)grow1 * N + gc) =
                    __floats2half2_rn(acc[nf][2], acc[nf][3]);
        }
    }
}

template <int NG, int KPAD, int FA>
__global__ __launch_bounds__(NG == 2 ? 256 : 128, NG == 2 ? 3 : 5)
void gemm_gat(const __half* __restrict__ featA, const __half* __restrict__ featH,
              const __half* __restrict__ Wt,
              const float* __restrict__ al, const float* __restrict__ ar,
              __half* __restrict__ hout,
              float* __restrict__ elp, float* __restrict__ erp) {
    gemm_body<NG, KPAD, FA>(blockIdx.x, featA, featH, Wt, al, ar, hout, elp, erp);
}

// ---------------- combined CSR scatter + t=0 layer-1 r/z GEMM ----------------
static const int SCAT_BLKS = (EE + 255) / 256;   // 3125
__global__ __launch_bounds__(256, 3)
void k_scatter_gemm(const int* __restrict__ src, const int* __restrict__ dst,
                    const __half* __restrict__ featA, const __half* __restrict__ featH,
                    const __half* __restrict__ Wt,
                    const float* __restrict__ al, const float* __restrict__ ar,
                    __half* __restrict__ hout,
                    float* __restrict__ elp, float* __restrict__ erp) {
    if (blockIdx.x < SCAT_BLKS) {
        int e = blockIdx.x * 256 + threadIdx.x;
        if (e < EE) {
            int d = dst[e];
            int pos = atomicAdd(&g_cursor[d], 1);
            g_colsrc[pos] = src[e];
        }
        return;
    }
    gemm_body<2, 80, 2>(blockIdx.x - SCAT_BLKS, featA, featH, Wt, al, ar,
                        hout, elp, erp);
}

// ---------------- r/z aggregation + fused GRU gate elementwise ----------------
// R12 half-warp scheme + mixed-precision FMA (no per-edge cvt chain).
// Lanes 0-15 own gate r, lanes 16-31 own gate z; batches of 16 edges; each half
// computes its own gate's weight (fp32 for the sum, fp16 bits for the FMA shfl).
__global__ void agg_rz(const __half2* __restrict__ h,
                       const float2* __restrict__ el2, const float2* __restrict__ er2,
                       const float* __restrict__ b,
                       const float* __restrict__ hx,
                       __half* __restrict__ rh16, float* __restrict__ zbuf) {
    int wid = (blockIdx.x * blockDim.x + threadIdx.x) >> 5;
    if (wid >= NN) return;
    const int lane = threadIdx.x & 31;
    const int beg = g_rowptr[wid];
    const int end = g_rowptr[wid + 1];
    const bool gz = lane >= 16;
    const int sub = lane & 15;
    const int wsrc = gz ? 16 : 0;
    const float2 er = er2[wid];
    const float erd = gz ? er.y : er.x;
    const int base = lane * 4;

    float wsum = 0.f;
    float f[4];
#pragma unroll
    for (int p = 0; p < 4; p++) f[p] = 0.f;

    for (int j0 = beg; j0 < end; j0 += 16) {
        int jj = j0 + sub;
        int sv = 0;
        float wv = 0.f;
        unsigned whb = 0;
        if (jj < end) {
            sv = g_colsrc[jj];
            float2 ev = el2[sv];
            float e = (gz ? ev.y : ev.x) + erd;
            e = e > 0.f ? e : 0.2f * e;
            wv = __expf(e);
            whb = __half_as_ushort(__float2half(wv));
        }
        wsum += wv;
        int cnt = end - j0; if (cnt > 16) cnt = 16;
#pragma unroll 4
        for (int i = 0; i < cnt; i++) {
            int s = __shfl_sync(0xffffffffu, sv, i);
            unsigned wb = __shfl_sync(0xffffffffu, whb, wsrc + i);
            uint2 u = *(const uint2*)(h + (size_t)s * 64 + lane * 2);
            fma4h(f, u, (unsigned short)wb);
        }
    }

    // reduce wsum within each 16-lane half
#pragma unroll
    for (int off = 1; off < 16; off <<= 1)
        wsum += __shfl_xor_sync(0xffffffffu, wsum, off);

    float inv = 1.f / fmaxf(wsum, 1e-9f);
    float g0 = 1.f / (1.f + __expf(-(f[0] * inv + b[base])));
    float g1 = 1.f / (1.f + __expf(-(f[1] * inv + b[base + 1])));
    float g2 = 1.f / (1.f + __expf(-(f[2] * inv + b[base + 2])));
    float g3 = 1.f / (1.f + __expf(-(f[3] * inv + b[base + 3])));
    if (!gz) {
        float4 hv = *(const float4*)(hx + (size_t)wid * 64 + base);
        __half2 r01 = __floats2half2_rn(g0 * hv.x, g1 * hv.y);
        __half2 r23 = __floats2half2_rn(g2 * hv.z, g3 * hv.w);
        uint2 st;
        st.x = *(unsigned*)&r01;
        st.y = *(unsigned*)&r23;
        *(uint2*)(rh16 + (size_t)wid * 64 + base) = st;
    } else {
        *(float4*)(zbuf + (size_t)wid * 64 + (base - 64)) = make_float4(g0, g1, g2, g3);
    }
}

// ---------------- candidate aggregation + fused GRU update (+ optional proj) --------
// R12 structure + mixed-precision FMA.
template <bool PROJ>
__global__ void agg_c(const __half2* __restrict__ h,
                      const float* __restrict__ el, const float* __restrict__ er,
                      const float* __restrict__ b2,
                      const float* __restrict__ zbuf,
                      float* __restrict__ hx, __half* __restrict__ hx16,
                      const float* __restrict__ pW, const float* __restrict__ pb,
                      float* __restrict__ outslice, __half* __restrict__ decin16) {
    int wid = (blockIdx.x * blockDim.x + threadIdx.x) >> 5;
    if (wid >= NN) return;
    const int lane = threadIdx.x & 31;
    const int beg = g_rowptr[wid];
    const int end = g_rowptr[wid + 1];
    const float erd = er[wid];
    const int base = lane * 2;

    float wsum = 0.f;
    float a0 = 0.f, a1 = 0.f;

    for (int j0 = beg; j0 < end; j0 += 32) {
        int jj = j0 + lane;
        int sv = 0;
        float wv = 0.f;
        unsigned whb = 0;
        if (jj < end) {
            sv = g_colsrc[jj];
            float e = el[sv] + erd; e = e > 0.f ? e : 0.2f * e;
            wv = __expf(e);
            whb = __half_as_ushort(__float2half(wv));
        }
        wsum += wv;
        int cnt = end - j0; if (cnt > 32) cnt = 32;
#pragma unroll 4
        for (int i = 0; i < cnt; i++) {
            int s = __shfl_sync(0xffffffffu, sv, i);
            unsigned wb = __shfl_sync(0xffffffffu, whb, i);
            unsigned u = *(const unsigned*)(h + (size_t)s * 32 + lane);
            fmah(a0, (unsigned short)u, (unsigned short)wb);
            fmah(a1, (unsigned short)(u >> 16), (unsigned short)wb);
        }
    }

#pragma unroll
    for (int off = 16; off > 0; off >>= 1)
        wsum += __shfl_xor_sync(0xffffffffu, wsum, off);

    float inv = 1.f / fmaxf(wsum, 1e-9f);
    float hc0 = tanhf(a0 * inv + b2[base]);
    float hc1 = tanhf(a1 * inv + b2[base + 1]);
    float2 z = *(const float2*)(zbuf + (size_t)wid * 64 + base);
    float2 hv = *(const float2*)(hx + (size_t)wid * 64 + base);
    float n0 = z.x * hv.x + (1.f - z.x) * hc0;
    float n1 = z.y * hv.y + (1.f - z.y) * hc1;
    *(float2*)(hx + (size_t)wid * 64 + base) = make_float2(n0, n1);
    *(__half2*)(hx16 + (size_t)wid * 64 + base) = __floats2half2_rn(n0, n1);

    if (PROJ) {
        float o0 = n0 * pW[2 * base] + n1 * pW[2 * base + 2];
        float o1 = n0 * pW[2 * base + 1] + n1 * pW[2 * base + 3];
#pragma unroll
        for (int off = 16; off > 0; off >>= 1) {
            o0 += __shfl_xor_sync(0xffffffffu, o0, off);
            o1 += __shfl_xor_sync(0xffffffffu, o1, off);
        }
        if (lane == 0) {
            o0 += pb[0];
            o1 += pb[1];
            outslice[2 * wid] = o0;
            outslice[2 * wid + 1] = o1;
            *(__half2*)(decin16 + (size_t)wid * 2) = __floats2half2_rn(o0, o1);
        }
    }
}

// ---------------- host orchestration ----------------
struct Scr {
    __half *hrz, *hc, *rh16;
    float *el2, *er2, *el0, *er0, *zbuf;
};
struct DevPtrs {
    int *deg, *rowptr, *cursor, *colsrc;
    float *h0, *h1;
    __half *h016, *h116, *decin16, *x16;
    Scr A, B;
    __half *We0rz, *We0c, *We1rz, *We1c, *Wd0rz, *Wd0c, *Wd1rz, *Wd1c;
};

static void get_ptrs(DevPtrs& P) {
    cudaGetSymbolAddress((void**)&P.deg, g_deg);
    cudaGetSymbolAddress((void**)&P.rowptr, g_rowptr);
    cudaGetSymbolAddress((void**)&P.cursor, g_cursor);
    cudaGetSymbolAddress((void**)&P.colsrc, g_colsrc);
    cudaGetSymbolAddress((void**)&P.h0, g_h0);
    cudaGetSymbolAddress((void**)&P.h1, g_h1);
    cudaGetSymbolAddress((void**)&P.h016, g_h016);
    cudaGetSymbolAddress((void**)&P.h116, g_h116);
    cudaGetSymbolAddress((void**)&P.decin16, g_decin16);
    cudaGetSymbolAddress((void**)&P.x16, g_x16);
    cudaGetSymbolAddress((void**)&P.A.hrz, g_hrzA);
    cudaGetSymbolAddress((void**)&P.A.hc, g_hcA);
    cudaGetSymbolAddress((void**)&P.A.rh16, g_rh16A);
    cudaGetSymbolAddress((void**)&P.A.el2, g_el2A);
    cudaGetSymbolAddress((void**)&P.A.er2, g_er2A);
    cudaGetSymbolAddress((void**)&P.A.el0, g_el0A);
    cudaGetSymbolAddress((void**)&P.A.er0, g_er0A);
    cudaGetSymbolAddress((void**)&P.A.zbuf, g_zbufA);
    cudaGetSymbolAddress((void**)&P.B.hrz, g_hrzB);
    cudaGetSymbolAddress((void**)&P.B.hc, g_hcB);
    cudaGetSymbolAddress((void**)&P.B.rh16, g_rh16B);
    cudaGetSymbolAddress((void**)&P.B.el2, g_el2B);
    cudaGetSymbolAddress((void**)&P.B.er2, g_er2B);
    cudaGetSymbolAddress((void**)&P.B.el0, g_el0B);
    cudaGetSymbolAddress((void**)&P.B.er0, g_er0B);
    cudaGetSymbolAddress((void**)&P.B.zbuf, g_zbufB);
    cudaGetSymbolAddress((void**)&P.We0rz, g_We0rz);
    cudaGetSymbolAddress((void**)&P.We0c, g_We0c);
    cudaGetSymbolAddress((void**)&P.We1rz, g_We1rz);
    cudaGetSymbolAddress((void**)&P.We1c, g_We1c);
    cudaGetSymbolAddress((void**)&P.Wd0rz, g_Wd0rz);
    cudaGetSymbolAddress((void**)&P.Wd0c, g_Wd0c);
    cudaGetSymbolAddress((void**)&P.Wd1rz, g_Wd1rz);
    cudaGetSymbolAddress((void**)&P.Wd1c, g_Wd1c);
}

static const int GEMM_BLKS = (NN + 63) / 64;   // 782
static const int AGG_BLKS = (NN + 7) / 8;
#define SMEM_SZ(NG_, KP_) ((size_t)((NG_) * 64 + 64) * ((KP_) + 8) * sizeof(__half))

static void L_gemm2_l1(cudaStream_t st, const Scr& S,
                       const __half* fa, const __half* fh, const __half* Wrz,
                       const float* al, const float* ar) {
    gemm_gat<2, 80, 2><<<GEMM_BLKS, 256, SMEM_SZ(2, 80), st>>>(
        fa, fh, Wrz, al, ar, S.hrz, S.el2, S.er2);
}
static void L_gemm1_l1(cudaStream_t st, const Scr& S,
                       const __half* fa, const __half* Wc,
                       const float* al, const float* ar) {
    gemm_gat<1, 80, 2><<<GEMM_BLKS, 128, SMEM_SZ(1, 80), st>>>(
        fa, S.rh16, Wc, al + 128, ar + 128, S.hc, S.el0, S.er0);
}
static void L_gemm2_l2(cudaStream_t st, const Scr& S,
                       const __half* fa, const __half* fh, const __half* Wrz,
                       const float* al, const float* ar) {
    gemm_gat<2, 128, 64><<<GEMM_BLKS, 256, SMEM_SZ(2, 128), st>>>(
        fa, fh, Wrz, al, ar, S.hrz, S.el2, S.er2);
}
static void L_gemm1_l2(cudaStream_t st, const Scr& S,
                       const __half* fa, const __half* Wc,
                       const float* al, const float* ar) {
    gemm_gat<1, 128, 64><<<GEMM_BLKS, 128, SMEM_SZ(1, 128), st>>>(
        fa, S.rh16, Wc, al + 128, ar + 128, S.hc, S.el0, S.er0);
}
static void L_aggrz(cudaStream_t st, const Scr& S, const float* b, const float* hx) {
    agg_rz<<<AGG_BLKS, 256, 0, st>>>((const __half2*)S.hrz, (const float2*)S.el2,
                                     (const float2*)S.er2, b, hx, S.rh16, S.zbuf);
}
static void L_aggc(cudaStream_t st, const DevPtrs& P, const Scr& S, const float* b,
                   float* hx, __half* hx16,
                   const float* pW = nullptr, const float* pb = nullptr,
                   float* outslice = nullptr) {
    if (outslice)
        agg_c<true><<<AGG_BLKS, 256, 0, st>>>((const __half2*)S.hc, S.el0, S.er0,
                                              b + 128, S.zbuf, hx, hx16, pW, pb,
                                              outslice, P.decin16);
    else
        agg_c<false><<<AGG_BLKS, 256, 0, st>>>((const __half2*)S.hc, S.el0, S.er0,
                                               b + 128, S.zbuf, hx, hx16,
                                               nullptr, nullptr, nullptr, nullptr);
}

extern "C" void kernel_launch(void* const* d_in, const int* in_sizes, int n_in,
                              void* d_out, int out_size) {
    (void)in_sizes; (void)n_in;
    const float* x = (const float*)d_in[0];
    const int* src = (const int*)d_in[1];
    const int* dst = (const int*)d_in[2];
    const float* enc_W0 = (const float*)d_in[3];
    const float* enc_al0 = (const float*)d_in[4];
    const float* enc_ar0 = (const float*)d_in[5];
    const float* enc_b0 = (const float*)d_in[6];
    const float* enc_W1 = (const float*)d_in[7];
    const float* enc_al1 = (const float*)d_in[8];
    const float* enc_ar1 = (const float*)d_in[9];
    const float* enc_b1 = (const float*)d_in[10];
    const float* dec_W0 = (const float*)d_in[11];
    const float* dec_al0 = (const float*)d_in[12];
    const float* dec_ar0 = (const float*)d_in[13];
    const float* dec_b0 = (const float*)d_in[14];
    const float* dec_W1 = (const float*)d_in[15];
    const float* dec_al1 = (const float*)d_in[16];
    const float* dec_ar1 = (const float*)d_in[17];
    const float* dec_b1 = (const float*)d_in[18];
    const float* proj_W = (const float*)d_in[19];
    const float* proj_b = (const float*)d_in[20];
    float* out = (float*)d_out;
    (void)out_size;

    static cudaStream_t s2 = nullptr;
    static cudaEvent_t ev1 = nullptr, ev2 = nullptr, ev3 = nullptr;
    if (!s2) {
        cudaStreamCreateWithFlags(&s2, cudaStreamNonBlocking);
        cudaEventCreateWithFlags(&ev1, cudaEventDisableTiming);
        cudaEventCreateWithFlags(&ev2, cudaEventDisableTiming);
        cudaEventCreateWithFlags(&ev3, cudaEventDisableTiming);
        cudaFuncSetAttribute((const void*)gemm_gat<2, 128, 64>,
                             cudaFuncAttributeMaxDynamicSharedMemorySize, 54 * 1024);
        cudaFuncSetAttribute((const void*)gemm_gat<1, 128, 64>,
                             cudaFuncAttributeMaxDynamicSharedMemorySize, 36 * 1024);
    }

    DevPtrs P;
    get_ptrs(P);
    cudaStream_t s0 = 0;

    // --- setup: 3 launches; launch #4 is agg_rz (profiled by ncu) ---
    k_setup<<<2048, 256, 0, s0>>>(x, dst, enc_W0, enc_W1, dec_W0, dec_W1,        // 1
                                  P.We0rz, P.We0c, P.We1rz, P.We1c,
                                  P.Wd0rz, P.Wd0c, P.Wd1rz, P.Wd1c,
                                  P.h0, P.h016, P.h1, P.h116, P.decin16, P.x16);
    k_scan<<<1, 1024, 0, s0>>>();                                                // 2
    k_scatter_gemm<<<SCAT_BLKS + GEMM_BLKS, 256, SMEM_SZ(2, 80), s0>>>(          // 3
        src, dst, P.x16, P.h016, P.We0rz, enc_al0, enc_ar0,
        P.A.hrz, P.A.el2, P.A.er2);

    // --- encoder t=0, layer 1 ---
    L_aggrz(s0, P.A, enc_b0, P.h0);                                              // 4 (profiled)
    L_gemm1_l1(s0, P.A, P.x16, P.We0c, enc_al0, enc_ar0);
    L_aggc(s0, P, P.A, enc_b0, P.h0, P.h016);
    cudaEventRecord(ev1, s0);

    // layer 2 t=0 on s2
    cudaStreamWaitEvent(s2, ev1, 0);
    L_gemm2_l2(s2, P.B, P.h016, P.h116, P.We1rz, enc_al1, enc_ar1);
    L_aggrz(s2, P.B, enc_b1, P.h1);
    L_gemm1_l2(s2, P.B, P.h016, P.We1c, enc_al1, enc_ar1);
    cudaEventRecord(ev2, s2);                   // last h016 read by layer2(t)
    L_aggc(s2, P, P.B, enc_b1, P.h1, P.h116);

    for (int t = 1; t < TT; t++) {
        const __half* xt = P.x16 + (size_t)t * NN * FF;
        L_gemm2_l1(s0, P.A, xt, P.h016, P.We0rz, enc_al0, enc_ar0);
        L_aggrz(s0, P.A, enc_b0, P.h0);
        L_gemm1_l1(s0, P.A, xt, P.We0c, enc_al0, enc_ar0);
        cudaStreamWaitEvent(s0, ev2, 0);        // layer2(t-1) done reading h016
        L_aggc(s0, P, P.A, enc_b0, P.h0, P.h016);
        cudaEventRecord(ev1, s0);
        cudaStreamWaitEvent(s2, ev1, 0);
        L_gemm2_l2(s2, P.B, P.h016, P.h116, P.We1rz, enc_al1, enc_ar1);
        L_aggrz(s2, P.B, enc_b1, P.h1);
        L_gemm1_l2(s2, P.B, P.h016, P.We1c, enc_al1, enc_ar1);
        cudaEventRecord(ev2, s2);
        L_aggc(s2, P, P.B, enc_b1, P.h1, P.h116);
    }

    cudaEventRecord(ev3, s2);
    cudaStreamWaitEvent(s0, ev3, 0);

    // --- decoder (serial on s0) ---
    for (int t = 0; t < HZ; t++) {
        L_gemm2_l1(s0, P.A, P.decin16, P.h016, P.Wd0rz, dec_al0, dec_ar0);
        L_aggrz(s0, P.A, dec_b0, P.h0);
        L_gemm1_l1(s0, P.A, P.decin16, P.Wd0c, dec_al0, dec_ar0);
        L_aggc(s0, P, P.A, dec_b0, P.h0, P.h016);
        L_gemm2_l2(s0, P.B, P.h016, P.h116, P.Wd1rz, dec_al1, dec_ar1);
        L_aggrz(s0, P.B, dec_b1, P.h1);
        L_gemm1_l2(s0, P.B, P.h016, P.Wd1c, dec_al1, dec_ar1);
        L_aggc(s0, P, P.B, dec_b1, P.h1, P.h116, proj_W, proj_b,
               out + (size_t)t * NN * DD);
    }

    // re-zero degree histogram for the next replay (stream-ordered after k_scan)
    k_zero_i<<<(NN + 255) / 256, 256, 0, s0>>>(P.deg, NN);
}